// round 14
// baseline (speedup 1.0000x reference)
#include <cuda_runtime.h>
#include <cuda_bf16.h>
#include <cuda_fp16.h>
#include <math.h>
#include <stdint.h>

#define NV 50000
#define NEDGE 800000
#define SLOPE 0.2f
#define BNEPS 1e-5f

// ---------------- scratch (device globals; no allocation allowed) ----------------
__device__ uint32_t g_zb[NV * 80];   // z packed fp16x2 (2 cols per word; layer2: 80 words)
__device__ float g_lin[NV * 160];    // lin = x @ Wl (fp32)
__device__ float g_bufB[NV * 128];   // layer output pre-BN
__device__ float g_el[NV * 4];
__device__ float g_er[NV * 4];
__device__ int g_src_s[NEDGE];
__device__ int g_rowptr[NV + 1];
__device__ int g_cnt[NV];
__device__ int g_woff[NV];
__device__ float g_bnsum[2][128];
__device__ float g_bnsq[2][128];
// pre-split weights: [matrix 0..5][n*128 + k]
__device__ __nv_bfloat16 g_wh[6][160 * 128];
__device__ __nv_bfloat16 g_wlo[6][160 * 128];
#define SCAN_CHUNK 4096
#define NSB ((NV + SCAN_CHUNK - 1) / SCAN_CHUNK)   // 13
__device__ int g_bsum[NSB];

// ---------------- helpers ----------------
__device__ __forceinline__ uint32_t pack_hi(float a, float b, float& ra, float& rb) {
    __nv_bfloat16 ha = __float2bfloat16(a), hb = __float2bfloat16(b);
    ra = a - __bfloat162float(ha);
    rb = b - __bfloat162float(hb);
    __nv_bfloat162 t;
    t.x = ha; t.y = hb;
    return *reinterpret_cast<uint32_t*>(&t);
}
__device__ __forceinline__ uint32_t pack_bf2(float a, float b) {
    __nv_bfloat162 t;
    t.x = __float2bfloat16(a); t.y = __float2bfloat16(b);
    return *reinterpret_cast<uint32_t*>(&t);
}
__device__ __forceinline__ uint32_t pack_h2(float a, float b) {
    __half2 t = __floats2half2_rn(a, b);
    return *reinterpret_cast<uint32_t*>(&t);
}
__device__ __forceinline__ float2 h2f(uint32_t u) {
    return __half22float2(*reinterpret_cast<__half2*>(&u));
}

__device__ __forceinline__ void mma_bf16(float* d, const uint32_t* a, const uint32_t* b) {
    asm volatile(
        "mma.sync.aligned.m16n8k16.row.col.f32.bf16.bf16.f32 "
        "{%0,%1,%2,%3}, {%4,%5,%6,%7}, {%8,%9}, {%0,%1,%2,%3};"
        : "+f"(d[0]), "+f"(d[1]), "+f"(d[2]), "+f"(d[3])
        : "r"(a[0]), "r"(a[1]), "r"(a[2]), "r"(a[3]), "r"(b[0]), "r"(b[1]));
}

__device__ __forceinline__ float sel4(float4 v, int h) {
    float r = v.x;
    r = (h == 1) ? v.y : r;
    r = (h == 2) ? v.z : r;
    r = (h == 3) ? v.w : r;
    return r;
}

// ---------------- W pre-split: all 6 matrices, one launch ----------------
__global__ void k_wprep_all(const float* __restrict__ W0, const float* __restrict__ W1,
                            const float* __restrict__ W2, const float* __restrict__ W3,
                            const float* __restrict__ W4, const float* __restrict__ W5) {
    int mi = blockIdx.y;
    const float* W = W0;
    if (mi == 1) W = W1;
    else if (mi == 2) W = W2;
    else if (mi == 3) W = W3;
    else if (mi == 4) W = W4;
    else if (mi == 5) W = W5;
    int NC = (mi >= 4) ? 160 : 128;
    int c = blockIdx.x * blockDim.x + threadIdx.x;
    if (c >= NC * 16) return;
    int n = c % NC, kg = c / NC;
    __nv_bfloat16 hi[8], lo[8];
#pragma unroll
    for (int i = 0; i < 8; i++) {
        float v = W[(size_t)(kg * 8 + i) * NC + n];
        __nv_bfloat16 h = __float2bfloat16(v);
        hi[i] = h;
        lo[i] = __float2bfloat16(v - __bfloat162float(h));
    }
    *(uint4*)&g_wh[mi][n * 128 + kg * 8] = *(uint4*)hi;
    *(uint4*)&g_wlo[mi][n * 128 + kg * 8] = *(uint4*)lo;
}

// ---------------- CSR build (counting sort by dst) ----------------
__global__ void k_zero_cnt() {
    int i = blockIdx.x * blockDim.x + threadIdx.x;
    if (i < NV) g_cnt[i] = 0;
    if (i < 128) {
        g_bnsum[0][i] = 0.f; g_bnsum[1][i] = 0.f;
        g_bnsq[0][i] = 0.f; g_bnsq[1][i] = 0.f;
    }
}

__global__ void k_hist(const int* __restrict__ dst) {
    int e = blockIdx.x * blockDim.x + threadIdx.x;
    if (e < NEDGE) atomicAdd(&g_cnt[dst[e]], 1);
}

__global__ __launch_bounds__(1024) void k_scan_p1() {
    __shared__ int ws[32];
    int tid = threadIdx.x, lane = tid & 31, wid = tid >> 5;
    int base = blockIdx.x * SCAN_CHUNK + tid * 4;
    int t = 0;
#pragma unroll
    for (int k = 0; k < 4; k++) {
        int i = base + k;
        if (i < NV) t += g_cnt[i];
    }
#pragma unroll
    for (int o = 16; o; o >>= 1) t += __shfl_xor_sync(0xffffffffu, t, o);
    if (lane == 0) ws[wid] = t;
    __syncthreads();
    if (wid == 0) {
        int x = ws[lane];
#pragma unroll
        for (int o = 16; o; o >>= 1) x += __shfl_xor_sync(0xffffffffu, x, o);
        if (lane == 0) g_bsum[blockIdx.x] = x;
    }
}

// p3 computes its own block offset from g_bsum (merged p2)
__global__ __launch_bounds__(1024) void k_scan_p3() {
    __shared__ int ws[32];
    __shared__ int s_bof;
    int tid = threadIdx.x, lane = tid & 31, wid = tid >> 5;

    if (wid == 0) {
        int v = (lane < NSB) ? g_bsum[lane] : 0;
        int x = v;
#pragma unroll
        for (int o = 1; o < 32; o <<= 1) {
            int t = __shfl_up_sync(0xffffffffu, x, o);
            if (lane >= o) x += t;
        }
        if (lane == blockIdx.x) s_bof = x - v;
        if (blockIdx.x == 0 && lane == NSB - 1) g_rowptr[NV] = x;
    }

    int base = blockIdx.x * SCAN_CHUNK + tid * 4;
    int c[4];
    int ts = 0;
#pragma unroll
    for (int k = 0; k < 4; k++) {
        int i = base + k;
        c[k] = (i < NV) ? g_cnt[i] : 0;
        ts += c[k];
    }
    int xi = ts;
#pragma unroll
    for (int o = 1; o < 32; o <<= 1) {
        int t = __shfl_up_sync(0xffffffffu, xi, o);
        if (lane >= o) xi += t;
    }
    if (lane == 31) ws[wid] = xi;
    __syncthreads();
    if (wid == 0) {
        int w = (lane < 32) ? ws[lane] : 0;
#pragma unroll
        for (int o = 1; o < 32; o <<= 1) {
            int t = __shfl_up_sync(0xffffffffu, w, o);
            if (lane >= o) w += t;
        }
        ws[lane] = w;
    }
    __syncthreads();
    int pre = s_bof + (wid ? ws[wid - 1] : 0) + xi - ts;
#pragma unroll
    for (int k = 0; k < 4; k++) {
        int i = base + k;
        if (i < NV) {
            g_rowptr[i] = pre;
            g_woff[i] = pre;
        }
        pre += c[k];
    }
}

__global__ void k_scatter(const int* __restrict__ src, const int* __restrict__ dst) {
    int e = blockIdx.x * blockDim.x + threadIdx.x;
    if (e >= NEDGE) return;
    int d = dst[e];
    int p = atomicAdd(&g_woff[d], 1);
    g_src_s[p] = src[e];
}

// ---------------- bf16x2-split tensor-core GEMM (mma.sync m16n8k16) ----------------
template <int NC, int MR>
__global__ __launch_bounds__(256, 1)
void k_gemm_mma(int useBufB, const float* __restrict__ Xarg, int wbase,
                const float* __restrict__ al, const float* __restrict__ ar,
                const float* __restrict__ gma, const float* __restrict__ bta, int bnl) {
    extern __shared__ char smem[];
    const float* X = useBufB ? g_bufB : Xarg;
    const int tid = threadIdx.x;
    const int m0 = blockIdx.x * MR;

    constexpr int STR = 272;
    constexpr int OFF_AH = 0;
    constexpr int OFF_AL = MR * STR;
    constexpr int OFF_BH = 2 * MR * STR;
    constexpr int OFF_BL = OFF_BH + NC * STR;
    constexpr int OFF_SC = OFF_BL + NC * STR;
    constexpr int OFF_SH = OFF_SC + 512;
    constexpr int NWM = MR / 32;
    constexpr int NWN = 8 / NWM;
    constexpr int NT = NC / NWN / 8;
    constexpr int DD = NC / 4;
    constexpr int HPW = (NC / NWN) / DD;

    const int lane = tid & 31, w = tid >> 5;
    const int mw = w % NWM, nw = w / NWM;
    const int nbase = nw * (NC / NWN);
    const int gr = lane >> 2, gc = (lane & 3) * 2;

    float* sSc = (float*)(smem + OFF_SC);
    float* sSh = (float*)(smem + OFF_SH);

    if (gma != nullptr) {
        if (tid < 128) {
            float mu = g_bnsum[bnl][tid] * (1.0f / NV);
            float var = g_bnsq[bnl][tid] * (1.0f / NV) - mu * mu;
            float sc = rsqrtf(var + BNEPS) * gma[tid];
            sSc[tid] = sc;
            sSh[tid] = bta[tid] - mu * sc;
        }
        __syncthreads();
    }

    for (int c = tid; c < MR * 16; c += 256) {
        int row = c >> 4, cg = c & 15;
        float v[8];
        if (m0 + row < NV) {
            const float4* p = (const float4*)(X + (size_t)(m0 + row) * 128 + cg * 8);
            float4 a = p[0], b = p[1];
            v[0] = a.x; v[1] = a.y; v[2] = a.z; v[3] = a.w;
            v[4] = b.x; v[5] = b.y; v[6] = b.z; v[7] = b.w;
            if (gma != nullptr) {
#pragma unroll
                for (int i = 0; i < 8; i++)
                    v[i] = fmaxf(v[i] * sSc[cg * 8 + i] + sSh[cg * 8 + i], 0.f);
            }
        } else {
#pragma unroll
            for (int i = 0; i < 8; i++) v[i] = 0.f;
        }
        uint4 hi, lo;
        float r0, r1;
        hi.x = pack_hi(v[0], v[1], r0, r1); lo.x = pack_bf2(r0, r1);
        hi.y = pack_hi(v[2], v[3], r0, r1); lo.y = pack_bf2(r0, r1);
        hi.z = pack_hi(v[4], v[5], r0, r1); lo.z = pack_bf2(r0, r1);
        hi.w = pack_hi(v[6], v[7], r0, r1); lo.w = pack_bf2(r0, r1);
        uint32_t o = (uint32_t)row * STR + cg * 16;
        *(uint4*)(smem + OFF_AH + o) = hi;
        *(uint4*)(smem + OFF_AL + o) = lo;
    }

#pragma unroll
    for (int mtx = 0; mtx < 2; mtx++) {
        const __nv_bfloat16* Wh = g_wh[wbase + mtx];
        const __nv_bfloat16* Wlo = g_wlo[wbase + mtx];
        __syncthreads();
        for (int c = tid; c < NC * 16; c += 256) {
            int kg = c & 15, n = c >> 4;
            uint4 hv = *(const uint4*)&Wh[n * 128 + kg * 8];
            uint4 lv = *(const uint4*)&Wlo[n * 128 + kg * 8];
            uint32_t o = (uint32_t)n * STR + kg * 16;
            *(uint4*)(smem + OFF_BH + o) = hv;
            *(uint4*)(smem + OFF_BL + o) = lv;
        }
        __syncthreads();

        float d[2][NT][4];
#pragma unroll
        for (int mt = 0; mt < 2; mt++)
#pragma unroll
            for (int nt = 0; nt < NT; nt++)
#pragma unroll
                for (int q = 0; q < 4; q++) d[mt][nt][q] = 0.f;

        for (int kt = 0; kt < 8; kt++) {
            int k0 = kt * 16;
            uint32_t ah[2][4], alo[2][4];
#pragma unroll
            for (int mt = 0; mt < 2; mt++) {
                int r = mw * 32 + mt * 16 + gr;
                uint32_t o00 = (uint32_t)r * STR + (k0 + gc) * 2;
                uint32_t o10 = o00 + 8 * STR;
                ah[mt][0] = *(const uint32_t*)(smem + OFF_AH + o00);
                ah[mt][1] = *(const uint32_t*)(smem + OFF_AH + o10);
                ah[mt][2] = *(const uint32_t*)(smem + OFF_AH + o00 + 16);
                ah[mt][3] = *(const uint32_t*)(smem + OFF_AH + o10 + 16);
                alo[mt][0] = *(const uint32_t*)(smem + OFF_AL + o00);
                alo[mt][1] = *(const uint32_t*)(smem + OFF_AL + o10);
                alo[mt][2] = *(const uint32_t*)(smem + OFF_AL + o00 + 16);
                alo[mt][3] = *(const uint32_t*)(smem + OFF_AL + o10 + 16);
            }
#pragma unroll
            for (int nt = 0; nt < NT; nt++) {
                int n = nbase + nt * 8 + gr;
                uint32_t ob = (uint32_t)n * STR + (k0 + gc) * 2;
                uint32_t bh[2], bl[2];
                bh[0] = *(const uint32_t*)(smem + OFF_BH + ob);
                bh[1] = *(const uint32_t*)(smem + OFF_BH + ob + 16);
                bl[0] = *(const uint32_t*)(smem + OFF_BL + ob);
                bl[1] = *(const uint32_t*)(smem + OFF_BL + ob + 16);
#pragma unroll
                for (int mt = 0; mt < 2; mt++) {
                    mma_bf16(d[mt][nt], ah[mt], bh);
                    mma_bf16(d[mt][nt], ah[mt], bl);
                    mma_bf16(d[mt][nt], alo[mt], bh);
                }
            }
        }

        // ---- store D: z -> packed fp16x2, lin -> fp32 ----
#pragma unroll
        for (int mt = 0; mt < 2; mt++) {
            int r0 = m0 + mw * 32 + mt * 16 + gr;
#pragma unroll
            for (int nt = 0; nt < NT; nt++) {
                int col = nbase + nt * 8 + gc;
                if (mtx == 0) {
                    if (r0 < NV)
                        g_zb[(size_t)r0 * (NC / 2) + col / 2] = pack_h2(d[mt][nt][0], d[mt][nt][1]);
                    if (r0 + 8 < NV)
                        g_zb[(size_t)(r0 + 8) * (NC / 2) + col / 2] = pack_h2(d[mt][nt][2], d[mt][nt][3]);
                } else {
                    if (r0 < NV)
                        *(float2*)(g_lin + (size_t)r0 * NC + col) =
                            make_float2(d[mt][nt][0], d[mt][nt][1]);
                    if (r0 + 8 < NV)
                        *(float2*)(g_lin + (size_t)(r0 + 8) * NC + col) =
                            make_float2(d[mt][nt][2], d[mt][nt][3]);
                }
            }
        }

        if (mtx == 0) {
            float elp[2][2][HPW], erp[2][2][HPW];
#pragma unroll
            for (int a = 0; a < 2; a++)
#pragma unroll
                for (int b = 0; b < 2; b++)
#pragma unroll
                    for (int c = 0; c < HPW; c++) { elp[a][b][c] = 0.f; erp[a][b][c] = 0.f; }
#pragma unroll
            for (int nt = 0; nt < NT; nt++) {
                int c0 = nbase + nt * 8 + gc;
                int hloc = (nt * 8) / DD;
                float a0 = __ldg(al + c0), a1 = __ldg(al + c0 + 1);
                float b0 = __ldg(ar + c0), b1 = __ldg(ar + c0 + 1);
#pragma unroll
                for (int mt = 0; mt < 2; mt++) {
                    elp[mt][0][hloc] += d[mt][nt][0] * a0 + d[mt][nt][1] * a1;
                    elp[mt][1][hloc] += d[mt][nt][2] * a0 + d[mt][nt][3] * a1;
                    erp[mt][0][hloc] += d[mt][nt][0] * b0 + d[mt][nt][1] * b1;
                    erp[mt][1][hloc] += d[mt][nt][2] * b0 + d[mt][nt][3] * b1;
                }
            }
#pragma unroll
            for (int off = 1; off <= 2; off <<= 1) {
#pragma unroll
                for (int a = 0; a < 2; a++)
#pragma unroll
                    for (int b = 0; b < 2; b++)
#pragma unroll
                        for (int c = 0; c < HPW; c++) {
                            elp[a][b][c] += __shfl_xor_sync(0xffffffffu, elp[a][b][c], off);
                            erp[a][b][c] += __shfl_xor_sync(0xffffffffu, erp[a][b][c], off);
                        }
            }
            if ((lane & 3) == 0) {
#pragma unroll
                for (int mt = 0; mt < 2; mt++)
#pragma unroll
                    for (int half = 0; half < 2; half++) {
                        int row = m0 + mw * 32 + mt * 16 + gr + half * 8;
                        if (row < NV) {
#pragma unroll
                            for (int hl = 0; hl < HPW; hl++) {
                                int hh = nw * HPW + hl;
                                g_el[row * 4 + hh] = elp[mt][half][hl];
                                g_er[row * 4 + hh] = erp[mt][half][hl];
                            }
                        }
                    }
            }
        }
    }
}

// ---------------- fused per-node softmax + aggregation + (non-final) BN partials ----------------
// One warp per node, all 4 heads, 8-edge unrolled main loop (latency amortization).
template <int DD, bool FINAL>
__global__ __launch_bounds__(256) void k_node(const float* __restrict__ bc,
                                              const float* __restrict__ bias_last,
                                              float* __restrict__ outp, int bnl) {
    constexpr int HD = 4 * DD;
    constexpr int HW = HD / 2;            // packed words per row (64 / 80)
    constexpr int NW = (HW + 31) / 32;    // words per lane (2 / 3)
    __shared__ float sh[FINAL ? 8 * HD : 8 * 128];
    int warp = threadIdx.x >> 5, lane = threadIdx.x & 31;
    int v = blockIdx.x * 8 + warp;        // grid is exactly NV/8
    int beg = g_rowptr[v], end = g_rowptr[v + 1];
    const int hq = lane & 3;

    float4 er4 = *(const float4*)(g_er + v * 4);
    float erh = sel4(er4, hq);

    int hsel[NW];
    bool wok[NW];
#pragma unroll
    for (int q = 0; q < NW; q++) {
        int wd = lane + 32 * q;
        wok[q] = (HW % 32 == 0) || (wd < HW);
        hsel[q] = wok[q] ? (2 * wd) / DD : 0;
    }

    float acc[NW][2];
#pragma unroll
    for (int q = 0; q < NW; q++) { acc[q][0] = 0.f; acc[q][1] = 0.f; }
    float s = 0.f;

    const uint32_t* zb = g_zb;
    int j = beg;

    // ---- 8-edge unrolled groups: all loads issued before any compute ----
    for (; j + 8 <= end; j += 8) {
        int sn[8];
#pragma unroll
        for (int u = 0; u < 8; u++) sn[u] = __ldg(&g_src_s[j + u]);
        float4 ee[8];
#pragma unroll
        for (int u = 0; u < 8; u++) ee[u] = *(const float4*)(g_el + sn[u] * 4);
        uint32_t zz[8][NW];
#pragma unroll
        for (int u = 0; u < 8; u++)
#pragma unroll
            for (int q = 0; q < NW; q++) {
                int wd = lane + 32 * q;
                zz[u][q] = wok[q] ? __ldg(zb + (size_t)sn[u] * HW + wd) : 0u;
            }
        float wgt[8];
#pragma unroll
        for (int u = 0; u < 8; u++) {
            float x = sel4(ee[u], hq) + erh;
            x = (x >= 0.f) ? x : SLOPE * x;
            wgt[u] = __expf(x);
        }
        s += ((wgt[0] + wgt[1]) + (wgt[2] + wgt[3])) +
             ((wgt[4] + wgt[5]) + (wgt[6] + wgt[7]));
#pragma unroll
        for (int q = 0; q < NW; q++) {
#pragma unroll
            for (int u = 0; u < 8; u++) {
                float a = __shfl_sync(0xffffffffu, wgt[u], hsel[q], 4);
                float2 f = h2f(zz[u][q]);
                acc[q][0] += a * f.x;
                acc[q][1] += a * f.y;
            }
        }
    }
    // ---- 4-edge remainder ----
    for (; j + 4 <= end; j += 4) {
        int sn0 = __ldg(&g_src_s[j]);
        int sn1 = __ldg(&g_src_s[j + 1]);
        int sn2 = __ldg(&g_src_s[j + 2]);
        int sn3 = __ldg(&g_src_s[j + 3]);
        float4 e0 = *(const float4*)(g_el + sn0 * 4);
        float4 e1 = *(const float4*)(g_el + sn1 * 4);
        float4 e2 = *(const float4*)(g_el + sn2 * 4);
        float4 e3 = *(const float4*)(g_el + sn3 * 4);
        uint32_t z0[NW], z1[NW], z2[NW], z3[NW];
#pragma unroll
        for (int q = 0; q < NW; q++) {
            int wd = lane + 32 * q;
            z0[q] = wok[q] ? __ldg(zb + (size_t)sn0 * HW + wd) : 0u;
            z1[q] = wok[q] ? __ldg(zb + (size_t)sn1 * HW + wd) : 0u;
            z2[q] = wok[q] ? __ldg(zb + (size_t)sn2 * HW + wd) : 0u;
            z3[q] = wok[q] ? __ldg(zb + (size_t)sn3 * HW + wd) : 0u;
        }
        float x0 = sel4(e0, hq) + erh; x0 = (x0 >= 0.f) ? x0 : SLOPE * x0;
        float x1 = sel4(e1, hq) + erh; x1 = (x1 >= 0.f) ? x1 : SLOPE * x1;
        float x2 = sel4(e2, hq) + erh; x2 = (x2 >= 0.f) ? x2 : SLOPE * x2;
        float x3 = sel4(e3, hq) + erh; x3 = (x3 >= 0.f) ? x3 : SLOPE * x3;
        float w0 = __expf(x0), w1 = __expf(x1), w2 = __expf(x2), w3 = __expf(x3);
        s += (w0 + w1) + (w2 + w3);
#pragma unroll
        for (int q = 0; q < NW; q++) {
            float a0 = __shfl_sync(0xffffffffu, w0, hsel[q], 4);
            float a1 = __shfl_sync(0xffffffffu, w1, hsel[q], 4);
            float a2 = __shfl_sync(0xffffffffu, w2, hsel[q], 4);
            float a3 = __shfl_sync(0xffffffffu, w3, hsel[q], 4);
            float2 f0 = h2f(z0[q]), f1 = h2f(z1[q]), f2 = h2f(z2[q]), f3 = h2f(z3[q]);
            acc[q][0] += (a0 * f0.x + a1 * f1.x) + (a2 * f2.x + a3 * f3.x);
            acc[q][1] += (a0 * f0.y + a1 * f1.y) + (a2 * f2.y + a3 * f3.y);
        }
    }
    // ---- scalar tail ----
    for (; j < end; j++) {
        int sn0 = __ldg(&g_src_s[j]);
        float4 e0 = *(const float4*)(g_el + sn0 * 4);
        uint32_t z0[NW];
#pragma unroll
        for (int q = 0; q < NW; q++) {
            int wd = lane + 32 * q;
            z0[q] = wok[q] ? __ldg(zb + (size_t)sn0 * HW + wd) : 0u;
        }
        float x0 = sel4(e0, hq) + erh; x0 = (x0 >= 0.f) ? x0 : SLOPE * x0;
        float w0 = __expf(x0);
        s += w0;
#pragma unroll
        for (int q = 0; q < NW; q++) {
            float a0 = __shfl_sync(0xffffffffu, w0, hsel[q], 4);
            float2 f0 = h2f(z0[q]);
            acc[q][0] += a0 * f0.x;
            acc[q][1] += a0 * f0.y;
        }
    }

    // every lane saw ALL edges -> s is complete for head (lane&3)
    float invh = (end > beg) ? 1.0f / s : 0.f;

    if (!FINAL) {
        float* bnS = sh;  // [8][128]
#pragma unroll
        for (int q = 0; q < NW; q++) {
            int wd = lane + 32 * q;
            int col = 2 * wd;
            float inv = __shfl_sync(0xffffffffu, invh, hsel[q], 4);
            float2 bcv = *(const float2*)(bc + col);
            float2 lv = *(const float2*)(g_lin + (size_t)v * HD + col);
            float v0 = acc[q][0] * inv + bcv.x + lv.x;
            float v1 = acc[q][1] * inv + bcv.y + lv.y;
            *(float2*)(g_bufB + (size_t)v * HD + col) = make_float2(v0, v1);
            bnS[warp * 128 + col] = v0;
            bnS[warp * 128 + col + 1] = v1;
        }
        __syncthreads();
        int t = threadIdx.x;
        if (t < 128) {
            float ss = 0.f, qq = 0.f;
#pragma unroll
            for (int g = 0; g < 8; g++) {
                float x = bnS[g * 128 + t];
                ss += x; qq += x * x;
            }
            atomicAdd(&g_bnsum[bnl][t], ss);
            atomicAdd(&g_bnsq[bnl][t], qq);
        }
    } else {
        float* swp = sh + warp * HD;
#pragma unroll
        for (int q = 0; q < NW; q++) {
            // shfl executed by ALL lanes (full mask) — must stay outside the wok guard
            float inv = __shfl_sync(0xffffffffu, invh, hsel[q], 4);
            if (wok[q]) {
                int wd = lane + 32 * q;
                int col = 2 * wd;
                swp[col] = acc[q][0] * inv + __ldg(bc + col) + g_lin[(size_t)v * HD + col];
                swp[col + 1] = acc[q][1] * inv + __ldg(bc + col + 1) +
                               g_lin[(size_t)v * HD + col + 1];
            }
        }
        __syncwarp();
        for (int c = lane; c < DD; c += 32) {
            float r = 0.25f * (swp[c] + swp[DD + c] + swp[2 * DD + c] + swp[3 * DD + c]) +
                      __ldg(bias_last + c);
            outp[(size_t)v * DD + c] = r;
        }
    }
}

// ---------------- driver ----------------
extern "C" void kernel_launch(void* const* d_in, const int* in_sizes, int n_in,
                              void* d_out, int out_size) {
    const float* feat = (const float*)d_in[0];
    const int* src = (const int*)d_in[1];
    const int* dst = (const int*)d_in[2];
    const float* Wc0 = (const float*)d_in[3];
    const float* al0 = (const float*)d_in[4];
    const float* ar0 = (const float*)d_in[5];
    const float* bc0 = (const float*)d_in[6];
    const float* Wl0 = (const float*)d_in[7];
    const float* Wc1 = (const float*)d_in[8];
    const float* al1 = (const float*)d_in[9];
    const float* ar1 = (const float*)d_in[10];
    const float* bc1 = (const float*)d_in[11];
    const float* Wl1 = (const float*)d_in[12];
    const float* Wc2 = (const float*)d_in[13];
    const float* al2 = (const float*)d_in[14];
    const float* ar2 = (const float*)d_in[15];
    const float* bc2 = (const float*)d_in[16];
    const float* Wl2 = (const float*)d_in[17];
    const float* g0 = (const float*)d_in[18];
    const float* b0 = (const float*)d_in[19];
    const float* g1 = (const float*)d_in[20];
    const float* b1 = (const float*)d_in[21];
    const float* bias_last = (const float*)d_in[22];
    float* out = (float*)d_out;

    static cudaStream_t s2 = nullptr;
    static cudaEvent_t evF = nullptr, evC = nullptr;
    if (s2 == nullptr) {
        cudaStreamCreate(&s2);
        cudaEventCreateWithFlags(&evF, cudaEventDisableTiming);
        cudaEventCreateWithFlags(&evC, cudaEventDisableTiming);
    }

    const int SMEM64 = 2 * 64 * 272 + 2 * 128 * 272 + 1024;    // 105472 -> 2 CTAs/SM
    const int SMEM160 = 2 * 128 * 272 + 2 * 160 * 272 + 1024;  // 157696
    cudaFuncSetAttribute((k_gemm_mma<128, 64>), cudaFuncAttributeMaxDynamicSharedMemorySize, SMEM64);
    cudaFuncSetAttribute((k_gemm_mma<160, 128>), cudaFuncAttributeMaxDynamicSharedMemorySize, SMEM160);

    // ---- fork: CSR build (+ BN zero) on side stream ----
    cudaEventRecord(evF, 0);
    cudaStreamWaitEvent(s2, evF, 0);
    k_zero_cnt<<<(NV + 255) / 256, 256, 0, s2>>>();
    k_hist<<<(NEDGE + 255) / 256, 256, 0, s2>>>(dst);
    k_scan_p1<<<NSB, 1024, 0, s2>>>();
    k_scan_p3<<<NSB, 1024, 0, s2>>>();
    k_scatter<<<(NEDGE + 255) / 256, 256, 0, s2>>>(src, dst);
    cudaEventRecord(evC, s2);

    // ---- main stream: W pre-split (single launch, all 6 matrices) ----
    {
        dim3 wg(10, 6);
        k_wprep_all<<<wg, 256>>>(Wc0, Wl0, Wc1, Wl1, Wc2, Wl2);
    }

    const int MT64 = (NV + 63) / 64;     // 782
    const int MT128 = (NV + 127) / 128;  // 391
    const int NODEG = NV / 8;            // 6250 exactly

    // ---- layer 0 (GEMM concurrent with CSR build) ----
    k_gemm_mma<128, 64><<<MT64, 256, SMEM64>>>(0, feat, 0, al0, ar0, nullptr, nullptr, 0);
    cudaStreamWaitEvent(0, evC, 0);  // join: k_node needs CSR + zeroed BN accumulators
    k_node<32, false><<<NODEG, 256>>>(bc0, nullptr, nullptr, 0);

    // ---- layer 1 (BN0+ReLU fused into A-load) ----
    k_gemm_mma<128, 64><<<MT64, 256, SMEM64>>>(1, nullptr, 2, al1, ar1, g0, b0, 0);
    k_node<32, false><<<NODEG, 256>>>(bc1, nullptr, nullptr, 1);

    // ---- layer 2 (BN1+ReLU fused; final: mean over heads + bias) ----
    k_gemm_mma<160, 128><<<MT128, 256, SMEM160>>>(1, nullptr, 4, al2, ar2, g1, b1, 1);
    k_node<40, true><<<NODEG, 256>>>(bc2, bias_last, out, 0);
}

// round 15
// speedup vs baseline: 1.5182x; 1.5182x over previous
#include <cuda_runtime.h>
#include <cuda_bf16.h>
#include <cuda_fp16.h>
#include <math.h>
#include <stdint.h>

#define NV 50000
#define NEDGE 800000
#define SLOPE 0.2f
#define BNEPS 1e-5f

// ---------------- scratch (device globals; no allocation allowed) ----------------
__device__ uint32_t g_zb[NV * 80];   // z packed fp16x2 (2 cols per word; layer2: 80 words)
__device__ float g_lin[NV * 160];    // lin = x @ Wl (fp32)
__device__ float g_bufB[NV * 128];   // layer output pre-BN
__device__ float g_el[NV * 4];
__device__ float g_er[NV * 4];
__device__ int g_src_s[NEDGE];
__device__ int g_rowptr[NV + 1];
__device__ int g_cnt[NV];
__device__ int g_woff[NV];
__device__ float g_bnsum[2][128];
__device__ float g_bnsq[2][128];
// pre-split weights: [matrix 0..5][n*128 + k]
__device__ __nv_bfloat16 g_wh[6][160 * 128];
__device__ __nv_bfloat16 g_wlo[6][160 * 128];
#define SCAN_CHUNK 4096
#define NSB ((NV + SCAN_CHUNK - 1) / SCAN_CHUNK)   // 13
__device__ int g_bsum[NSB];

// ---------------- helpers ----------------
__device__ __forceinline__ uint32_t pack_hi(float a, float b, float& ra, float& rb) {
    __nv_bfloat16 ha = __float2bfloat16(a), hb = __float2bfloat16(b);
    ra = a - __bfloat162float(ha);
    rb = b - __bfloat162float(hb);
    __nv_bfloat162 t;
    t.x = ha; t.y = hb;
    return *reinterpret_cast<uint32_t*>(&t);
}
__device__ __forceinline__ uint32_t pack_bf2(float a, float b) {
    __nv_bfloat162 t;
    t.x = __float2bfloat16(a); t.y = __float2bfloat16(b);
    return *reinterpret_cast<uint32_t*>(&t);
}
__device__ __forceinline__ uint32_t pack_h2(float a, float b) {
    __half2 t = __floats2half2_rn(a, b);
    return *reinterpret_cast<uint32_t*>(&t);
}
__device__ __forceinline__ float2 h2f(uint32_t u) {
    return __half22float2(*reinterpret_cast<__half2*>(&u));
}

__device__ __forceinline__ void mma_bf16(float* d, const uint32_t* a, const uint32_t* b) {
    asm volatile(
        "mma.sync.aligned.m16n8k16.row.col.f32.bf16.bf16.f32 "
        "{%0,%1,%2,%3}, {%4,%5,%6,%7}, {%8,%9}, {%0,%1,%2,%3};"
        : "+f"(d[0]), "+f"(d[1]), "+f"(d[2]), "+f"(d[3])
        : "r"(a[0]), "r"(a[1]), "r"(a[2]), "r"(a[3]), "r"(b[0]), "r"(b[1]));
}

__device__ __forceinline__ float sel4(float4 v, int h) {
    float r = v.x;
    r = (h == 1) ? v.y : r;
    r = (h == 2) ? v.z : r;
    r = (h == 3) ? v.w : r;
    return r;
}

// ---------------- W pre-split (mi0 selects starting matrix) ----------------
__global__ void k_wprep(const float* __restrict__ W0, const float* __restrict__ W1,
                        const float* __restrict__ W2, const float* __restrict__ W3,
                        int mi0) {
    int mi = mi0 + blockIdx.y;
    const float* W = W0;
    if (blockIdx.y == 1) W = W1;
    else if (blockIdx.y == 2) W = W2;
    else if (blockIdx.y == 3) W = W3;
    int NC = (mi >= 4) ? 160 : 128;
    int c = blockIdx.x * blockDim.x + threadIdx.x;
    if (c >= NC * 16) return;
    int n = c % NC, kg = c / NC;
    __nv_bfloat16 hi[8], lo[8];
#pragma unroll
    for (int i = 0; i < 8; i++) {
        float v = W[(size_t)(kg * 8 + i) * NC + n];
        __nv_bfloat16 h = __float2bfloat16(v);
        hi[i] = h;
        lo[i] = __float2bfloat16(v - __bfloat162float(h));
    }
    *(uint4*)&g_wh[mi][n * 128 + kg * 8] = *(uint4*)hi;
    *(uint4*)&g_wlo[mi][n * 128 + kg * 8] = *(uint4*)lo;
}

// ---------------- CSR build (counting sort by dst) ----------------
__global__ void k_zero_cnt() {
    int i = blockIdx.x * blockDim.x + threadIdx.x;
    if (i < NV) g_cnt[i] = 0;
    if (i < 128) {
        g_bnsum[0][i] = 0.f; g_bnsum[1][i] = 0.f;
        g_bnsq[0][i] = 0.f; g_bnsq[1][i] = 0.f;
    }
}

__global__ void k_hist(const int* __restrict__ dst) {
    int e = blockIdx.x * blockDim.x + threadIdx.x;
    if (e < NEDGE) atomicAdd(&g_cnt[dst[e]], 1);
}

__global__ __launch_bounds__(1024) void k_scan_p1() {
    __shared__ int ws[32];
    int tid = threadIdx.x, lane = tid & 31, wid = tid >> 5;
    int base = blockIdx.x * SCAN_CHUNK + tid * 4;
    int t = 0;
#pragma unroll
    for (int k = 0; k < 4; k++) {
        int i = base + k;
        if (i < NV) t += g_cnt[i];
    }
#pragma unroll
    for (int o = 16; o; o >>= 1) t += __shfl_xor_sync(0xffffffffu, t, o);
    if (lane == 0) ws[wid] = t;
    __syncthreads();
    if (wid == 0) {
        int x = ws[lane];
#pragma unroll
        for (int o = 16; o; o >>= 1) x += __shfl_xor_sync(0xffffffffu, x, o);
        if (lane == 0) g_bsum[blockIdx.x] = x;
    }
}

// p3 computes its own block offset from g_bsum (merged p2)
__global__ __launch_bounds__(1024) void k_scan_p3() {
    __shared__ int ws[32];
    __shared__ int s_bof;
    int tid = threadIdx.x, lane = tid & 31, wid = tid >> 5;

    if (wid == 0) {
        int v = (lane < NSB) ? g_bsum[lane] : 0;
        int x = v;
#pragma unroll
        for (int o = 1; o < 32; o <<= 1) {
            int t = __shfl_up_sync(0xffffffffu, x, o);
            if (lane >= o) x += t;
        }
        if (lane == blockIdx.x) s_bof = x - v;
        if (blockIdx.x == 0 && lane == NSB - 1) g_rowptr[NV] = x;
    }

    int base = blockIdx.x * SCAN_CHUNK + tid * 4;
    int c[4];
    int ts = 0;
#pragma unroll
    for (int k = 0; k < 4; k++) {
        int i = base + k;
        c[k] = (i < NV) ? g_cnt[i] : 0;
        ts += c[k];
    }
    int xi = ts;
#pragma unroll
    for (int o = 1; o < 32; o <<= 1) {
        int t = __shfl_up_sync(0xffffffffu, xi, o);
        if (lane >= o) xi += t;
    }
    if (lane == 31) ws[wid] = xi;
    __syncthreads();
    if (wid == 0) {
        int w = (lane < 32) ? ws[lane] : 0;
#pragma unroll
        for (int o = 1; o < 32; o <<= 1) {
            int t = __shfl_up_sync(0xffffffffu, w, o);
            if (lane >= o) w += t;
        }
        ws[lane] = w;
    }
    __syncthreads();
    int pre = s_bof + (wid ? ws[wid - 1] : 0) + xi - ts;
#pragma unroll
    for (int k = 0; k < 4; k++) {
        int i = base + k;
        if (i < NV) {
            g_rowptr[i] = pre;
            g_woff[i] = pre;
        }
        pre += c[k];
    }
}

__global__ void k_scatter(const int* __restrict__ src, const int* __restrict__ dst) {
    int e = blockIdx.x * blockDim.x + threadIdx.x;
    if (e >= NEDGE) return;
    int d = dst[e];
    int p = atomicAdd(&g_woff[d], 1);
    g_src_s[p] = src[e];
}

// ---------------- bf16x2-split tensor-core GEMM (mma.sync m16n8k16) ----------------
template <int NC, int MR>
__global__ __launch_bounds__(256, 1)
void k_gemm_mma(int useBufB, const float* __restrict__ Xarg, int wbase,
                const float* __restrict__ al, const float* __restrict__ ar,
                const float* __restrict__ gma, const float* __restrict__ bta, int bnl) {
    extern __shared__ char smem[];
    const float* X = useBufB ? g_bufB : Xarg;
    const int tid = threadIdx.x;
    const int m0 = blockIdx.x * MR;

    constexpr int STR = 272;
    constexpr int OFF_AH = 0;
    constexpr int OFF_AL = MR * STR;
    constexpr int OFF_BH = 2 * MR * STR;
    constexpr int OFF_BL = OFF_BH + NC * STR;
    constexpr int OFF_SC = OFF_BL + NC * STR;
    constexpr int OFF_SH = OFF_SC + 512;
    constexpr int NWM = MR / 32;
    constexpr int NWN = 8 / NWM;
    constexpr int NT = NC / NWN / 8;
    constexpr int DD = NC / 4;
    constexpr int HPW = (NC / NWN) / DD;

    const int lane = tid & 31, w = tid >> 5;
    const int mw = w % NWM, nw = w / NWM;
    const int nbase = nw * (NC / NWN);
    const int gr = lane >> 2, gc = (lane & 3) * 2;

    float* sSc = (float*)(smem + OFF_SC);
    float* sSh = (float*)(smem + OFF_SH);

    if (gma != nullptr) {
        if (tid < 128) {
            float mu = g_bnsum[bnl][tid] * (1.0f / NV);
            float var = g_bnsq[bnl][tid] * (1.0f / NV) - mu * mu;
            float sc = rsqrtf(var + BNEPS) * gma[tid];
            sSc[tid] = sc;
            sSh[tid] = bta[tid] - mu * sc;
        }
        __syncthreads();
    }

    for (int c = tid; c < MR * 16; c += 256) {
        int row = c >> 4, cg = c & 15;
        float v[8];
        if (m0 + row < NV) {
            const float4* p = (const float4*)(X + (size_t)(m0 + row) * 128 + cg * 8);
            float4 a = p[0], b = p[1];
            v[0] = a.x; v[1] = a.y; v[2] = a.z; v[3] = a.w;
            v[4] = b.x; v[5] = b.y; v[6] = b.z; v[7] = b.w;
            if (gma != nullptr) {
#pragma unroll
                for (int i = 0; i < 8; i++)
                    v[i] = fmaxf(v[i] * sSc[cg * 8 + i] + sSh[cg * 8 + i], 0.f);
            }
        } else {
#pragma unroll
            for (int i = 0; i < 8; i++) v[i] = 0.f;
        }
        uint4 hi, lo;
        float r0, r1;
        hi.x = pack_hi(v[0], v[1], r0, r1); lo.x = pack_bf2(r0, r1);
        hi.y = pack_hi(v[2], v[3], r0, r1); lo.y = pack_bf2(r0, r1);
        hi.z = pack_hi(v[4], v[5], r0, r1); lo.z = pack_bf2(r0, r1);
        hi.w = pack_hi(v[6], v[7], r0, r1); lo.w = pack_bf2(r0, r1);
        uint32_t o = (uint32_t)row * STR + cg * 16;
        *(uint4*)(smem + OFF_AH + o) = hi;
        *(uint4*)(smem + OFF_AL + o) = lo;
    }

#pragma unroll
    for (int mtx = 0; mtx < 2; mtx++) {
        const __nv_bfloat16* Wh = g_wh[wbase + mtx];
        const __nv_bfloat16* Wlo = g_wlo[wbase + mtx];
        __syncthreads();
        for (int c = tid; c < NC * 16; c += 256) {
            int kg = c & 15, n = c >> 4;
            uint4 hv = *(const uint4*)&Wh[n * 128 + kg * 8];
            uint4 lv = *(const uint4*)&Wlo[n * 128 + kg * 8];
            uint32_t o = (uint32_t)n * STR + kg * 16;
            *(uint4*)(smem + OFF_BH + o) = hv;
            *(uint4*)(smem + OFF_BL + o) = lv;
        }
        __syncthreads();

        float d[2][NT][4];
#pragma unroll
        for (int mt = 0; mt < 2; mt++)
#pragma unroll
            for (int nt = 0; nt < NT; nt++)
#pragma unroll
                for (int q = 0; q < 4; q++) d[mt][nt][q] = 0.f;

        for (int kt = 0; kt < 8; kt++) {
            int k0 = kt * 16;
            uint32_t ah[2][4], alo[2][4];
#pragma unroll
            for (int mt = 0; mt < 2; mt++) {
                int r = mw * 32 + mt * 16 + gr;
                uint32_t o00 = (uint32_t)r * STR + (k0 + gc) * 2;
                uint32_t o10 = o00 + 8 * STR;
                ah[mt][0] = *(const uint32_t*)(smem + OFF_AH + o00);
                ah[mt][1] = *(const uint32_t*)(smem + OFF_AH + o10);
                ah[mt][2] = *(const uint32_t*)(smem + OFF_AH + o00 + 16);
                ah[mt][3] = *(const uint32_t*)(smem + OFF_AH + o10 + 16);
                alo[mt][0] = *(const uint32_t*)(smem + OFF_AL + o00);
                alo[mt][1] = *(const uint32_t*)(smem + OFF_AL + o10);
                alo[mt][2] = *(const uint32_t*)(smem + OFF_AL + o00 + 16);
                alo[mt][3] = *(const uint32_t*)(smem + OFF_AL + o10 + 16);
            }
#pragma unroll
            for (int nt = 0; nt < NT; nt++) {
                int n = nbase + nt * 8 + gr;
                uint32_t ob = (uint32_t)n * STR + (k0 + gc) * 2;
                uint32_t bh[2], bl[2];
                bh[0] = *(const uint32_t*)(smem + OFF_BH + ob);
                bh[1] = *(const uint32_t*)(smem + OFF_BH + ob + 16);
                bl[0] = *(const uint32_t*)(smem + OFF_BL + ob);
                bl[1] = *(const uint32_t*)(smem + OFF_BL + ob + 16);
#pragma unroll
                for (int mt = 0; mt < 2; mt++) {
                    mma_bf16(d[mt][nt], ah[mt], bh);
                    mma_bf16(d[mt][nt], ah[mt], bl);
                    mma_bf16(d[mt][nt], alo[mt], bh);
                }
            }
        }

        // ---- store D: z -> packed fp16x2, lin -> fp32 ----
#pragma unroll
        for (int mt = 0; mt < 2; mt++) {
            int r0 = m0 + mw * 32 + mt * 16 + gr;
#pragma unroll
            for (int nt = 0; nt < NT; nt++) {
                int col = nbase + nt * 8 + gc;
                if (mtx == 0) {
                    if (r0 < NV)
                        g_zb[(size_t)r0 * (NC / 2) + col / 2] = pack_h2(d[mt][nt][0], d[mt][nt][1]);
                    if (r0 + 8 < NV)
                        g_zb[(size_t)(r0 + 8) * (NC / 2) + col / 2] = pack_h2(d[mt][nt][2], d[mt][nt][3]);
                } else {
                    if (r0 < NV)
                        *(float2*)(g_lin + (size_t)r0 * NC + col) =
                            make_float2(d[mt][nt][0], d[mt][nt][1]);
                    if (r0 + 8 < NV)
                        *(float2*)(g_lin + (size_t)(r0 + 8) * NC + col) =
                            make_float2(d[mt][nt][2], d[mt][nt][3]);
                }
            }
        }

        if (mtx == 0) {
            float elp[2][2][HPW], erp[2][2][HPW];
#pragma unroll
            for (int a = 0; a < 2; a++)
#pragma unroll
                for (int b = 0; b < 2; b++)
#pragma unroll
                    for (int c = 0; c < HPW; c++) { elp[a][b][c] = 0.f; erp[a][b][c] = 0.f; }
#pragma unroll
            for (int nt = 0; nt < NT; nt++) {
                int c0 = nbase + nt * 8 + gc;
                int hloc = (nt * 8) / DD;
                float a0 = __ldg(al + c0), a1 = __ldg(al + c0 + 1);
                float b0 = __ldg(ar + c0), b1 = __ldg(ar + c0 + 1);
#pragma unroll
                for (int mt = 0; mt < 2; mt++) {
                    elp[mt][0][hloc] += d[mt][nt][0] * a0 + d[mt][nt][1] * a1;
                    elp[mt][1][hloc] += d[mt][nt][2] * a0 + d[mt][nt][3] * a1;
                    erp[mt][0][hloc] += d[mt][nt][0] * b0 + d[mt][nt][1] * b1;
                    erp[mt][1][hloc] += d[mt][nt][2] * b0 + d[mt][nt][3] * b1;
                }
            }
#pragma unroll
            for (int off = 1; off <= 2; off <<= 1) {
#pragma unroll
                for (int a = 0; a < 2; a++)
#pragma unroll
                    for (int b = 0; b < 2; b++)
#pragma unroll
                        for (int c = 0; c < HPW; c++) {
                            elp[a][b][c] += __shfl_xor_sync(0xffffffffu, elp[a][b][c], off);
                            erp[a][b][c] += __shfl_xor_sync(0xffffffffu, erp[a][b][c], off);
                        }
            }
            if ((lane & 3) == 0) {
#pragma unroll
                for (int mt = 0; mt < 2; mt++)
#pragma unroll
                    for (int half = 0; half < 2; half++) {
                        int row = m0 + mw * 32 + mt * 16 + gr + half * 8;
                        if (row < NV) {
#pragma unroll
                            for (int hl = 0; hl < HPW; hl++) {
                                int hh = nw * HPW + hl;
                                g_el[row * 4 + hh] = elp[mt][half][hl];
                                g_er[row * 4 + hh] = erp[mt][half][hl];
                            }
                        }
                    }
            }
        }
    }
}

// ---------------- fused per-node softmax + aggregation + (non-final) BN partials ----------------
// One warp per node, all 4 heads; 4-edge unroll (proven optimum — 8-edge spilled regs).
template <int DD, bool FINAL>
__global__ __launch_bounds__(256) void k_node(const float* __restrict__ bc,
                                              const float* __restrict__ bias_last,
                                              float* __restrict__ outp, int bnl) {
    constexpr int HD = 4 * DD;
    constexpr int HW = HD / 2;            // packed words per row (64 / 80)
    constexpr int NW = (HW + 31) / 32;    // words per lane (2 / 3)
    __shared__ float sh[FINAL ? 8 * HD : 8 * 128];
    int warp = threadIdx.x >> 5, lane = threadIdx.x & 31;
    int v = blockIdx.x * 8 + warp;        // grid is exactly NV/8
    int beg = g_rowptr[v], end = g_rowptr[v + 1];
    const int hq = lane & 3;

    float4 er4 = *(const float4*)(g_er + v * 4);
    float erh = sel4(er4, hq);

    int hsel[NW];
    bool wok[NW];
#pragma unroll
    for (int q = 0; q < NW; q++) {
        int wd = lane + 32 * q;
        wok[q] = (HW % 32 == 0) || (wd < HW);
        hsel[q] = wok[q] ? (2 * wd) / DD : 0;
    }

    float acc[NW][2];
#pragma unroll
    for (int q = 0; q < NW; q++) { acc[q][0] = 0.f; acc[q][1] = 0.f; }
    float s = 0.f;

    const uint32_t* zb = g_zb;
    int j = beg;
    for (; j + 4 <= end; j += 4) {
        int sn0 = __ldg(&g_src_s[j]);
        int sn1 = __ldg(&g_src_s[j + 1]);
        int sn2 = __ldg(&g_src_s[j + 2]);
        int sn3 = __ldg(&g_src_s[j + 3]);
        float4 e0 = *(const float4*)(g_el + sn0 * 4);
        float4 e1 = *(const float4*)(g_el + sn1 * 4);
        float4 e2 = *(const float4*)(g_el + sn2 * 4);
        float4 e3 = *(const float4*)(g_el + sn3 * 4);
        uint32_t z0[NW], z1[NW], z2[NW], z3[NW];
#pragma unroll
        for (int q = 0; q < NW; q++) {
            int wd = lane + 32 * q;
            z0[q] = wok[q] ? __ldg(zb + (size_t)sn0 * HW + wd) : 0u;
            z1[q] = wok[q] ? __ldg(zb + (size_t)sn1 * HW + wd) : 0u;
            z2[q] = wok[q] ? __ldg(zb + (size_t)sn2 * HW + wd) : 0u;
            z3[q] = wok[q] ? __ldg(zb + (size_t)sn3 * HW + wd) : 0u;
        }
        float x0 = sel4(e0, hq) + erh; x0 = (x0 >= 0.f) ? x0 : SLOPE * x0;
        float x1 = sel4(e1, hq) + erh; x1 = (x1 >= 0.f) ? x1 : SLOPE * x1;
        float x2 = sel4(e2, hq) + erh; x2 = (x2 >= 0.f) ? x2 : SLOPE * x2;
        float x3 = sel4(e3, hq) + erh; x3 = (x3 >= 0.f) ? x3 : SLOPE * x3;
        float w0 = __expf(x0), w1 = __expf(x1), w2 = __expf(x2), w3 = __expf(x3);
        s += (w0 + w1) + (w2 + w3);
#pragma unroll
        for (int q = 0; q < NW; q++) {
            float a0 = __shfl_sync(0xffffffffu, w0, hsel[q], 4);
            float a1 = __shfl_sync(0xffffffffu, w1, hsel[q], 4);
            float a2 = __shfl_sync(0xffffffffu, w2, hsel[q], 4);
            float a3 = __shfl_sync(0xffffffffu, w3, hsel[q], 4);
            float2 f0 = h2f(z0[q]), f1 = h2f(z1[q]), f2 = h2f(z2[q]), f3 = h2f(z3[q]);
            acc[q][0] += (a0 * f0.x + a1 * f1.x) + (a2 * f2.x + a3 * f3.x);
            acc[q][1] += (a0 * f0.y + a1 * f1.y) + (a2 * f2.y + a3 * f3.y);
        }
    }
    for (; j < end; j++) {
        int sn0 = __ldg(&g_src_s[j]);
        float4 e0 = *(const float4*)(g_el + sn0 * 4);
        uint32_t z0[NW];
#pragma unroll
        for (int q = 0; q < NW; q++) {
            int wd = lane + 32 * q;
            z0[q] = wok[q] ? __ldg(zb + (size_t)sn0 * HW + wd) : 0u;
        }
        float x0 = sel4(e0, hq) + erh; x0 = (x0 >= 0.f) ? x0 : SLOPE * x0;
        float w0 = __expf(x0);
        s += w0;
#pragma unroll
        for (int q = 0; q < NW; q++) {
            float a0 = __shfl_sync(0xffffffffu, w0, hsel[q], 4);
            float2 f0 = h2f(z0[q]);
            acc[q][0] += a0 * f0.x;
            acc[q][1] += a0 * f0.y;
        }
    }

    // every lane saw ALL edges -> s is complete for head (lane&3)
    float invh = (end > beg) ? 1.0f / s : 0.f;

    if (!FINAL) {
        float* bnS = sh;  // [8][128]
#pragma unroll
        for (int q = 0; q < NW; q++) {
            int wd = lane + 32 * q;
            int col = 2 * wd;
            float inv = __shfl_sync(0xffffffffu, invh, hsel[q], 4);
            float2 bcv = *(const float2*)(bc + col);
            float2 lv = *(const float2*)(g_lin + (size_t)v * HD + col);
            float v0 = acc[q][0] * inv + bcv.x + lv.x;
            float v1 = acc[q][1] * inv + bcv.y + lv.y;
            *(float2*)(g_bufB + (size_t)v * HD + col) = make_float2(v0, v1);
            bnS[warp * 128 + col] = v0;
            bnS[warp * 128 + col + 1] = v1;
        }
        __syncthreads();
        int t = threadIdx.x;
        if (t < 128) {
            float ss = 0.f, qq = 0.f;
#pragma unroll
            for (int g = 0; g < 8; g++) {
                float x = bnS[g * 128 + t];
                ss += x; qq += x * x;
            }
            atomicAdd(&g_bnsum[bnl][t], ss);
            atomicAdd(&g_bnsq[bnl][t], qq);
        }
    } else {
        float* swp = sh + warp * HD;
#pragma unroll
        for (int q = 0; q < NW; q++) {
            // shfl executed by ALL lanes (full mask) — must stay outside the wok guard
            float inv = __shfl_sync(0xffffffffu, invh, hsel[q], 4);
            if (wok[q]) {
                int wd = lane + 32 * q;
                int col = 2 * wd;
                swp[col] = acc[q][0] * inv + __ldg(bc + col) + g_lin[(size_t)v * HD + col];
                swp[col + 1] = acc[q][1] * inv + __ldg(bc + col + 1) +
                               g_lin[(size_t)v * HD + col + 1];
            }
        }
        __syncwarp();
        for (int c = lane; c < DD; c += 32) {
            float r = 0.25f * (swp[c] + swp[DD + c] + swp[2 * DD + c] + swp[3 * DD + c]) +
                      __ldg(bias_last + c);
            outp[(size_t)v * DD + c] = r;
        }
    }
}

// ---------------- driver ----------------
extern "C" void kernel_launch(void* const* d_in, const int* in_sizes, int n_in,
                              void* d_out, int out_size) {
    const float* feat = (const float*)d_in[0];
    const int* src = (const int*)d_in[1];
    const int* dst = (const int*)d_in[2];
    const float* Wc0 = (const float*)d_in[3];
    const float* al0 = (const float*)d_in[4];
    const float* ar0 = (const float*)d_in[5];
    const float* bc0 = (const float*)d_in[6];
    const float* Wl0 = (const float*)d_in[7];
    const float* Wc1 = (const float*)d_in[8];
    const float* al1 = (const float*)d_in[9];
    const float* ar1 = (const float*)d_in[10];
    const float* bc1 = (const float*)d_in[11];
    const float* Wl1 = (const float*)d_in[12];
    const float* Wc2 = (const float*)d_in[13];
    const float* al2 = (const float*)d_in[14];
    const float* ar2 = (const float*)d_in[15];
    const float* bc2 = (const float*)d_in[16];
    const float* Wl2 = (const float*)d_in[17];
    const float* g0 = (const float*)d_in[18];
    const float* b0 = (const float*)d_in[19];
    const float* g1 = (const float*)d_in[20];
    const float* b1 = (const float*)d_in[21];
    const float* bias_last = (const float*)d_in[22];
    float* out = (float*)d_out;

    static cudaStream_t s2 = nullptr, s3 = nullptr;
    static cudaEvent_t evF = nullptr, evC = nullptr, evW = nullptr;
    if (s2 == nullptr) {
        cudaStreamCreate(&s2);
        cudaStreamCreate(&s3);
        cudaEventCreateWithFlags(&evF, cudaEventDisableTiming);
        cudaEventCreateWithFlags(&evC, cudaEventDisableTiming);
        cudaEventCreateWithFlags(&evW, cudaEventDisableTiming);
    }

    const int SMEM64 = 2 * 64 * 272 + 2 * 128 * 272 + 1024;    // 105472 -> 2 CTAs/SM
    const int SMEM160 = 2 * 128 * 272 + 2 * 160 * 272 + 1024;  // 157696
    cudaFuncSetAttribute((k_gemm_mma<128, 64>), cudaFuncAttributeMaxDynamicSharedMemorySize, SMEM64);
    cudaFuncSetAttribute((k_gemm_mma<160, 128>), cudaFuncAttributeMaxDynamicSharedMemorySize, SMEM160);

    // ---- fork: CSR build (+ BN zero) on side stream s2 ----
    cudaEventRecord(evF, 0);
    cudaStreamWaitEvent(s2, evF, 0);
    cudaStreamWaitEvent(s3, evF, 0);
    k_zero_cnt<<<(NV + 255) / 256, 256, 0, s2>>>();
    k_hist<<<(NEDGE + 255) / 256, 256, 0, s2>>>(dst);
    k_scan_p1<<<NSB, 1024, 0, s2>>>();
    k_scan_p3<<<NSB, 1024, 0, s2>>>();
    k_scatter<<<(NEDGE + 255) / 256, 256, 0, s2>>>(src, dst);
    cudaEventRecord(evC, s2);

    // ---- s3: W pre-split for layers 1,2 (matrices 2..5) — off the GEMM-0 path ----
    {
        dim3 wg(10, 4);
        k_wprep<<<wg, 256, 0, s3>>>(Wc1, Wl1, Wc2, Wl2, 2);
        cudaEventRecord(evW, s3);
    }

    // ---- main stream: W pre-split for layer 0 only (matrices 0,1) ----
    {
        dim3 wg(8, 2);
        k_wprep<<<wg, 256>>>(Wc0, Wl0, nullptr, nullptr, 0);
    }

    const int MT64 = (NV + 63) / 64;     // 782
    const int MT128 = (NV + 127) / 128;  // 391
    const int NODEG = NV / 8;            // 6250 exactly

    // ---- layer 0 (GEMM concurrent with CSR build) ----
    k_gemm_mma<128, 64><<<MT64, 256, SMEM64>>>(0, feat, 0, al0, ar0, nullptr, nullptr, 0);
    cudaStreamWaitEvent(0, evC, 0);  // join: k_node needs CSR + zeroed BN accumulators
    k_node<32, false><<<NODEG, 256>>>(bc0, nullptr, nullptr, 0);

    // ---- layer 1 (BN0+ReLU fused into A-load; needs matrices 2,3) ----
    cudaStreamWaitEvent(0, evW, 0);
    k_gemm_mma<128, 64><<<MT64, 256, SMEM64>>>(1, nullptr, 2, al1, ar1, g0, b0, 0);
    k_node<32, false><<<NODEG, 256>>>(bc1, nullptr, nullptr, 1);

    // ---- layer 2 (BN1+ReLU fused; final: mean over heads + bias) ----
    k_gemm_mma<160, 128><<<MT128, 256, SMEM160>>>(1, nullptr, 4, al2, ar2, g1, b1, 1);
    k_node<40, true><<<NODEG, 256>>>(bc2, bias_last, out, 0);
}